// round 6
// baseline (speedup 1.0000x reference)
#include <cuda_runtime.h>
#include <math.h>

#define Nn 50000
#define Ee 1600000
#define DIN 128
#define DH 64
#define BN_EPS 1e-5f

// ---------------- scratch (device globals; no allocation allowed) -------------
__device__ float g_w[Ee];          // mixed weight, then full edge norm
__device__ int2  g_idx[Ee];        // (src, dst) as int32
__device__ float g_deg[Nn];        // degree, then dinv (in place)
__device__ float g_h1[Nn * DH];    // x @ W1
__device__ float g_agg1[Nn * DH];  // layer-1 aggregation (incl. self loop + b1)
__device__ float g_h2[Nn * DH];
__device__ float g_agg2[Nn * DH];
__device__ float g_sum1[DH], g_sq1[DH], g_sum2[DH], g_sq2[DH];
__device__ float g_a;              // sigmoid(alpha)
__device__ int   g_is64;           // 1 if edge_index stored as int64

// ---------------- dtype detection: int64 vs int32 edge indices ---------------
__global__ void detect_kernel(const unsigned* __restrict__ ei) {
    __shared__ unsigned sh[256];
    unsigned o = 0;
    // OR the would-be high words of the first 4096 int64 entries. If the tensor
    // is int64 these are all 0; if int32 they are random node ids (all-zero
    // probability ~0). Reads stay within 8192 u32 words < 2*Ee either way.
    for (int i = threadIdx.x; i < 4096; i += 256) o |= ei[2 * i + 1];
    sh[threadIdx.x] = o;
    __syncthreads();
    if (threadIdx.x == 0) {
        unsigned t = 0;
        for (int i = 0; i < 256; i++) t |= sh[i];
        g_is64 = (t == 0) ? 1 : 0;
    }
}

// ---------------- init: deg=1 (self loops), zero BN stats, sigmoid(alpha) ----
__global__ void init_kernel(const float* __restrict__ alpha) {
    int i = blockIdx.x * blockDim.x + threadIdx.x;
    if (i < Nn) g_deg[i] = 1.0f;
    if (i < DH) { g_sum1[i] = 0.f; g_sq1[i] = 0.f; g_sum2[i] = 0.f; g_sq2[i] = 0.f; }
    if (i == 0) g_a = 1.0f / (1.0f + expf(-alpha[0]));
}

// ---------------- mix weights, record (src,dst), accumulate degree -----------
__global__ void mix_deg_kernel(const void* __restrict__ ei,
                               const float* __restrict__ wsc,
                               const float* __restrict__ wfc) {
    int e = blockIdx.x * blockDim.x + threadIdx.x;
    if (e >= Ee) return;
    int s, d;
    if (g_is64) {
        const unsigned* u = (const unsigned*)ei;
        s = (int)u[2 * (size_t)e];
        d = (int)u[2 * ((size_t)Ee + e)];
    } else {
        const int* p = (const int*)ei;
        s = p[e];
        d = p[Ee + e];
    }
    float a = g_a;
    float w = a * wsc[e] + (1.0f - a) * wfc[e];
    g_w[e] = w;
    g_idx[e] = make_int2(s, d);
    atomicAdd(&g_deg[d], w);
}

__global__ void dinv_kernel() {
    int i = blockIdx.x * blockDim.x + threadIdx.x;
    if (i < Nn) {
        float d = g_deg[i];
        g_deg[i] = (d > 0.f) ? rsqrtf(fmaxf(d, 1e-12f)) : 0.f;
    }
}

__global__ void norm_kernel() {
    int e = blockIdx.x * blockDim.x + threadIdx.x;
    if (e < Ee) {
        int2 sd = g_idx[e];
        g_w[e] = g_w[e] * g_deg[sd.x] * g_deg[sd.y];
    }
}

// ---------------- GEMM1: h1 = x @ W1 ; agg1 = h1*dinv^2 + b1 -----------------
__global__ void gemm1_kernel(const float* __restrict__ x,
                             const float* __restrict__ W1,
                             const float* __restrict__ b1) {
    __shared__ float sW[DIN * DH];      // 32 KB
    __shared__ float sx[32][DIN];       // 16 KB
    int tid = threadIdx.x;
    for (int i = tid; i < DIN * DH; i += 256) sW[i] = W1[i];
    __syncthreads();
    int warp = tid >> 5, lane = tid & 31;

    for (int base = blockIdx.x * 32; base < Nn; base += gridDim.x * 32) {
        int r0 = base + warp * 4;
        #pragma unroll
        for (int r = 0; r < 4; r++) {
            int row = r0 + r;
            if (row < Nn) {
                #pragma unroll
                for (int j = 0; j < 4; j++)
                    sx[warp * 4 + r][lane + j * 32] = x[(size_t)row * DIN + lane + j * 32];
            }
        }
        __syncwarp();

        float acc[4][2] = {};
        #pragma unroll 8
        for (int k4 = 0; k4 < DIN / 4; k4++) {
            float4 xv[4];
            #pragma unroll
            for (int r = 0; r < 4; r++)
                xv[r] = *reinterpret_cast<const float4*>(&sx[warp * 4 + r][k4 * 4]);
            #pragma unroll
            for (int kk = 0; kk < 4; kk++) {
                int k = k4 * 4 + kk;
                float w0 = sW[k * DH + lane];
                float w1v = sW[k * DH + lane + 32];
                #pragma unroll
                for (int r = 0; r < 4; r++) {
                    float xs = (kk == 0) ? xv[r].x : (kk == 1) ? xv[r].y : (kk == 2) ? xv[r].z : xv[r].w;
                    acc[r][0] = fmaf(xs, w0, acc[r][0]);
                    acc[r][1] = fmaf(xs, w1v, acc[r][1]);
                }
            }
        }

        #pragma unroll
        for (int r = 0; r < 4; r++) {
            int row = r0 + r;
            if (row < Nn) {
                float di = g_deg[row];
                float sn = di * di;   // self-loop norm: dinv[i]*1*dinv[i]
                g_h1[row * DH + lane] = acc[r][0];
                g_h1[row * DH + lane + 32] = acc[r][1];
                g_agg1[row * DH + lane] = fmaf(acc[r][0], sn, b1[lane]);
                g_agg1[row * DH + lane + 32] = fmaf(acc[r][1], sn, b1[lane + 32]);
            }
        }
        __syncwarp();
    }
}

// ---------------- edge scatter: agg[dst] += h[src] * norm --------------------
// 16 threads per edge; each thread covers 4 floats of the 64-float row with a
// single red.global.add.v4.f32 (no return -> no scoreboard wait on the store).
template <int L>
__global__ void scatter_kernel() {
    const float* __restrict__ h = (L == 1) ? g_h1 : g_h2;
    float* agg = (L == 1) ? g_agg1 : g_agg2;
    int gti = blockIdx.x * blockDim.x + threadIdx.x;
    int grp = gti >> 4;
    int l4 = (threadIdx.x & 15) * 4;
    int stride = (gridDim.x * blockDim.x) >> 4;
    #pragma unroll 2
    for (int e = grp; e < Ee; e += stride) {
        const int2 sd = g_idx[e];
        const float nrm = g_w[e];
        float4 v = *reinterpret_cast<const float4*>(h + (size_t)sd.x * DH + l4);
        float* dp = agg + (size_t)sd.y * DH + l4;
        asm volatile("red.global.add.v4.f32 [%0], {%1,%2,%3,%4};"
                     :: "l"(dp), "f"(v.x * nrm), "f"(v.y * nrm), "f"(v.z * nrm), "f"(v.w * nrm)
                     : "memory");
    }
}

// ---------------- BN column stats (sum, sumsq) -------------------------------
template <int L>
__global__ void stats_kernel() {
    const float* __restrict__ agg = (L == 1) ? g_agg1 : g_agg2;
    float* sum = (L == 1) ? g_sum1 : g_sum2;
    float* sq  = (L == 1) ? g_sq1  : g_sq2;
    int tid = threadIdx.x;
    int c = tid & 63, grp = tid >> 6;
    float s = 0.f, q = 0.f;
    for (int r = blockIdx.x * 4 + grp; r < Nn; r += gridDim.x * 4) {
        float v = agg[(size_t)r * DH + c];
        s += v;
        q = fmaf(v, v, q);
    }
    __shared__ float ss[256], sqv[256];
    ss[tid] = s; sqv[tid] = q;
    __syncthreads();
    if (tid < 64) {
        float S = ss[tid] + ss[tid + 64] + ss[tid + 128] + ss[tid + 192];
        float Q = sqv[tid] + sqv[tid + 64] + sqv[tid + 128] + sqv[tid + 192];
        atomicAdd(&sum[tid], S);
        atomicAdd(&sq[tid], Q);
    }
}

// ---------------- GEMM2: h2 = relu(bn1(agg1)) @ W2 ; agg2 = h2*dinv^2 + b2 ---
__global__ void gemm2_kernel(const float* __restrict__ W2,
                             const float* __restrict__ b2,
                             const float* __restrict__ gamma1,
                             const float* __restrict__ beta1) {
    __shared__ float sW[DH * DH];   // 16 KB
    __shared__ float sx[32][DH];    // 8 KB
    __shared__ float s_scale[DH], s_shift[DH];
    int tid = threadIdx.x;
    if (tid < DH) {
        float mean = g_sum1[tid] * (1.0f / Nn);
        float var = g_sq1[tid] * (1.0f / Nn) - mean * mean;
        float sc = gamma1[tid] * rsqrtf(var + BN_EPS);
        s_scale[tid] = sc;
        s_shift[tid] = fmaf(-mean, sc, beta1[tid]);
    }
    for (int i = tid; i < DH * DH; i += 256) sW[i] = W2[i];
    __syncthreads();
    int warp = tid >> 5, lane = tid & 31;

    for (int base = blockIdx.x * 32; base < Nn; base += gridDim.x * 32) {
        int r0 = base + warp * 4;
        #pragma unroll
        for (int r = 0; r < 4; r++) {
            int row = r0 + r;
            if (row < Nn) {
                #pragma unroll
                for (int j = 0; j < 2; j++) {
                    int c = lane + j * 32;
                    float v = g_agg1[(size_t)row * DH + c];
                    sx[warp * 4 + r][c] = fmaxf(fmaf(v, s_scale[c], s_shift[c]), 0.f);
                }
            }
        }
        __syncwarp();

        float acc[4][2] = {};
        #pragma unroll 4
        for (int k4 = 0; k4 < DH / 4; k4++) {
            float4 xv[4];
            #pragma unroll
            for (int r = 0; r < 4; r++)
                xv[r] = *reinterpret_cast<const float4*>(&sx[warp * 4 + r][k4 * 4]);
            #pragma unroll
            for (int kk = 0; kk < 4; kk++) {
                int k = k4 * 4 + kk;
                float w0 = sW[k * DH + lane];
                float w1v = sW[k * DH + lane + 32];
                #pragma unroll
                for (int r = 0; r < 4; r++) {
                    float xs = (kk == 0) ? xv[r].x : (kk == 1) ? xv[r].y : (kk == 2) ? xv[r].z : xv[r].w;
                    acc[r][0] = fmaf(xs, w0, acc[r][0]);
                    acc[r][1] = fmaf(xs, w1v, acc[r][1]);
                }
            }
        }

        #pragma unroll
        for (int r = 0; r < 4; r++) {
            int row = r0 + r;
            if (row < Nn) {
                float di = g_deg[row];
                float sn = di * di;
                g_h2[row * DH + lane] = acc[r][0];
                g_h2[row * DH + lane + 32] = acc[r][1];
                g_agg2[row * DH + lane] = fmaf(acc[r][0], sn, b2[lane]);
                g_agg2[row * DH + lane + 32] = fmaf(acc[r][1], sn, b2[lane + 32]);
            }
        }
        __syncwarp();
    }
}

// ---------------- final: out = relu(bn2(agg2)) -------------------------------
__global__ void final_kernel(const float* __restrict__ gamma2,
                             const float* __restrict__ beta2,
                             float* __restrict__ out) {
    __shared__ float s_scale[DH], s_shift[DH];
    int tid = threadIdx.x;
    if (tid < DH) {
        float mean = g_sum2[tid] * (1.0f / Nn);
        float var = g_sq2[tid] * (1.0f / Nn) - mean * mean;
        float sc = gamma2[tid] * rsqrtf(var + BN_EPS);
        s_scale[tid] = sc;
        s_shift[tid] = fmaf(-mean, sc, beta2[tid]);
    }
    __syncthreads();
    int i = blockIdx.x * 256 + tid;
    if (i < Nn * DH) {
        int c = i & 63;
        out[i] = fmaxf(fmaf(g_agg2[i], s_scale[c], s_shift[c]), 0.f);
    }
}

// -----------------------------------------------------------------------------
extern "C" void kernel_launch(void* const* d_in, const int* in_sizes, int n_in,
                              void* d_out, int out_size) {
    const float* x      = (const float*)d_in[0];
    const void*  ei_sc  = d_in[1];
    const float* w_sc   = (const float*)d_in[2];
    // d_in[3] = edge_index_fc (unused by reference)
    const float* w_fc   = (const float*)d_in[4];
    const float* alpha  = (const float*)d_in[5];
    const float* W1     = (const float*)d_in[6];
    const float* b1     = (const float*)d_in[7];
    const float* W2     = (const float*)d_in[8];
    const float* b2     = (const float*)d_in[9];
    const float* gamma1 = (const float*)d_in[10];
    const float* beta1  = (const float*)d_in[11];
    const float* gamma2 = (const float*)d_in[12];
    const float* beta2  = (const float*)d_in[13];
    float* out = (float*)d_out;

    const int TB = 256;
    const int nblkN = (Nn + TB - 1) / TB;       // 196
    const int nblkE = (Ee + TB - 1) / TB;       // 6250

    detect_kernel<<<1, TB>>>((const unsigned*)ei_sc);
    init_kernel<<<nblkN, TB>>>(alpha);
    mix_deg_kernel<<<nblkE, TB>>>(ei_sc, w_sc, w_fc);
    dinv_kernel<<<nblkN, TB>>>();
    norm_kernel<<<nblkE, TB>>>();
    gemm1_kernel<<<592, TB>>>(x, W1, b1);
    scatter_kernel<1><<<1184, TB>>>();
    stats_kernel<1><<<1024, TB>>>();
    gemm2_kernel<<<592, TB>>>(W2, b2, gamma1, beta1);
    scatter_kernel<2><<<1184, TB>>>();
    stats_kernel<2><<<1024, TB>>>();
    final_kernel<<<(Nn * DH + TB - 1) / TB, TB>>>(gamma2, beta2, out);
}

// round 8
// speedup vs baseline: 1.3457x; 1.3457x over previous
#include <cuda_runtime.h>
#include <math.h>

#define Nn 50000
#define Ee 1600000
#define DIN 128
#define DH 64
#define BN_EPS 1e-5f

// ---------------- scratch (device globals; no allocation allowed) -------------
__device__ float g_w[Ee];            // mixed weight (pre-norm)
__device__ int2  g_idx[Ee];          // (src, dst) as int32
__device__ int2  g_csr[Ee];          // dst-sorted: (src, bitcast(norm))
__device__ int   g_cnt[Nn];          // per-dst edge count
__device__ int   g_part[50176];      // block-local exclusive scan
__device__ int   g_bsum[196], g_boff[256];
__device__ int   g_row_off[Nn + 1];  // CSR row offsets
__device__ int   g_cursor[Nn];       // fill cursors
__device__ float g_deg[Nn];          // degree, then dinv (in place)
__device__ float g_h1[Nn * DH];      // x @ W1
__device__ float g_agg1[Nn * DH];
__device__ float g_h2[Nn * DH];
__device__ float g_agg2[Nn * DH];
__device__ float g_sum1[DH], g_sq1[DH], g_sum2[DH], g_sq2[DH];
__device__ float g_a;
__device__ int   g_is64;

// ---------------- dtype detection: int64 vs int32 edge indices ---------------
__global__ void detect_kernel(const unsigned* __restrict__ ei) {
    __shared__ unsigned sh[256];
    unsigned o = 0;
    for (int i = threadIdx.x; i < 4096; i += 256) o |= ei[2 * i + 1];
    sh[threadIdx.x] = o;
    __syncthreads();
    if (threadIdx.x == 0) {
        unsigned t = 0;
        for (int i = 0; i < 256; i++) t |= sh[i];
        g_is64 = (t == 0) ? 1 : 0;
    }
}

// ---------------- init -------------------------------------------------------
__global__ void init_kernel(const float* __restrict__ alpha) {
    int i = blockIdx.x * blockDim.x + threadIdx.x;
    if (i < Nn) { g_deg[i] = 1.0f; g_cnt[i] = 0; }
    if (i < DH) { g_sum1[i] = 0.f; g_sq1[i] = 0.f; g_sum2[i] = 0.f; g_sq2[i] = 0.f; }
    if (i == 0) g_a = 1.0f / (1.0f + expf(-alpha[0]));
}

// ---------------- mix weights, record (src,dst), degree + count --------------
__global__ void mix_deg_kernel(const void* __restrict__ ei,
                               const float* __restrict__ wsc,
                               const float* __restrict__ wfc) {
    int e = blockIdx.x * blockDim.x + threadIdx.x;
    if (e >= Ee) return;
    int s, d;
    if (g_is64) {
        const unsigned* u = (const unsigned*)ei;
        s = (int)u[2 * (size_t)e];
        d = (int)u[2 * ((size_t)Ee + e)];
    } else {
        const int* p = (const int*)ei;
        s = p[e];
        d = p[Ee + e];
    }
    float a = g_a;
    float w = a * wsc[e] + (1.0f - a) * wfc[e];
    g_w[e] = w;
    g_idx[e] = make_int2(s, d);
    atomicAdd(&g_deg[d], w);
    atomicAdd(&g_cnt[d], 1);
}

__global__ void dinv_kernel() {
    int i = blockIdx.x * blockDim.x + threadIdx.x;
    if (i < Nn) {
        float d = g_deg[i];
        g_deg[i] = (d > 0.f) ? rsqrtf(fmaxf(d, 1e-12f)) : 0.f;
    }
}

// ---------------- scan (exclusive prefix of counts -> row offsets) -----------
__global__ void scan_a_kernel() {
    __shared__ int s[256];
    int i = blockIdx.x * 256 + threadIdx.x;
    int v = (i < Nn) ? g_cnt[i] : 0;
    s[threadIdx.x] = v;
    __syncthreads();
    #pragma unroll
    for (int off = 1; off < 256; off <<= 1) {
        int t = (threadIdx.x >= off) ? s[threadIdx.x - off] : 0;
        __syncthreads();
        s[threadIdx.x] += t;
        __syncthreads();
    }
    g_part[i] = s[threadIdx.x] - v;          // exclusive within block
    if (threadIdx.x == 255) g_bsum[blockIdx.x] = s[255];
}

__global__ void scan_b_kernel() {
    __shared__ int s[256];
    int v = (threadIdx.x < 196) ? g_bsum[threadIdx.x] : 0;
    s[threadIdx.x] = v;
    __syncthreads();
    #pragma unroll
    for (int off = 1; off < 256; off <<= 1) {
        int t = (threadIdx.x >= off) ? s[threadIdx.x - off] : 0;
        __syncthreads();
        s[threadIdx.x] += t;
        __syncthreads();
    }
    g_boff[threadIdx.x] = s[threadIdx.x] - v;
}

__global__ void scan_c_kernel() {
    int i = blockIdx.x * 256 + threadIdx.x;
    if (i < Nn) {
        int o = g_part[i] + g_boff[blockIdx.x];
        g_row_off[i] = o;
        g_cursor[i] = o;
    }
    if (i == 0) g_row_off[Nn] = Ee;
}

// ---------------- CSR fill: norm computed here -------------------------------
__global__ void fill_kernel() {
    int e = blockIdx.x * blockDim.x + threadIdx.x;
    if (e >= Ee) return;
    int2 sd = g_idx[e];
    float nrm = g_w[e] * g_deg[sd.x] * g_deg[sd.y];
    int pos = atomicAdd(&g_cursor[sd.y], 1);
    g_csr[pos] = make_int2(sd.x, __float_as_int(nrm));
}

// ---------------- GEMM1: h1 = x @ W1 -----------------------------------------
__global__ void gemm1_kernel(const float* __restrict__ x,
                             const float* __restrict__ W1) {
    __shared__ float sW[DIN * DH];      // 32 KB
    __shared__ float sx[32][DIN];       // 16 KB
    int tid = threadIdx.x;
    for (int i = tid; i < DIN * DH; i += 256) sW[i] = W1[i];
    __syncthreads();
    int warp = tid >> 5, lane = tid & 31;

    for (int base = blockIdx.x * 32; base < Nn; base += gridDim.x * 32) {
        int r0 = base + warp * 4;
        #pragma unroll
        for (int r = 0; r < 4; r++) {
            int row = r0 + r;
            if (row < Nn) {
                #pragma unroll
                for (int j = 0; j < 4; j++)
                    sx[warp * 4 + r][lane + j * 32] = x[(size_t)row * DIN + lane + j * 32];
            }
        }
        __syncwarp();

        float acc[4][2] = {};
        #pragma unroll 8
        for (int k4 = 0; k4 < DIN / 4; k4++) {
            float4 xv[4];
            #pragma unroll
            for (int r = 0; r < 4; r++)
                xv[r] = *reinterpret_cast<const float4*>(&sx[warp * 4 + r][k4 * 4]);
            #pragma unroll
            for (int kk = 0; kk < 4; kk++) {
                int k = k4 * 4 + kk;
                float w0 = sW[k * DH + lane];
                float w1v = sW[k * DH + lane + 32];
                #pragma unroll
                for (int r = 0; r < 4; r++) {
                    float xs = (kk == 0) ? xv[r].x : (kk == 1) ? xv[r].y : (kk == 2) ? xv[r].z : xv[r].w;
                    acc[r][0] = fmaf(xs, w0, acc[r][0]);
                    acc[r][1] = fmaf(xs, w1v, acc[r][1]);
                }
            }
        }

        #pragma unroll
        for (int r = 0; r < 4; r++) {
            int row = r0 + r;
            if (row < Nn) {
                g_h1[row * DH + lane] = acc[r][0];
                g_h1[row * DH + lane + 32] = acc[r][1];
            }
        }
        __syncwarp();
    }
}

// ---------------- CSR aggregation + fused BN stats ---------------------------
// One warp per dst row. Lanes 0-15 / 16-31 each cover all 64 cols (float4/lane)
// and process alternating edges; final shfl_xor(16) combines the halves.
template <int L>
__global__ void agg_kernel(const float* __restrict__ bias) {
    const float* __restrict__ h = (L == 1) ? g_h1 : g_h2;
    float* agg  = (L == 1) ? g_agg1 : g_agg2;
    float* gsum = (L == 1) ? g_sum1 : g_sum2;
    float* gsq  = (L == 1) ? g_sq1  : g_sq2;

    int tid = threadIdx.x;
    int lane = tid & 31, half = lane >> 4;
    int l4 = (lane & 15) * 4;
    int wg = (blockIdx.x * blockDim.x + tid) >> 5;
    int nw = (gridDim.x * blockDim.x) >> 5;
    float4 bb = *reinterpret_cast<const float4*>(bias + l4);
    float ls0 = 0, ls1 = 0, ls2 = 0, ls3 = 0;
    float lq0 = 0, lq1 = 0, lq2 = 0, lq3 = 0;

    for (int r = wg; r < Nn; r += nw) {
        int beg = g_row_off[r], end = g_row_off[r + 1];
        float4 acc, acc2 = make_float4(0.f, 0.f, 0.f, 0.f);
        if (half == 0) {
            float di = g_deg[r];
            float sn = di * di;  // self-loop: dinv*1*dinv
            float4 hv = *reinterpret_cast<const float4*>(h + (size_t)r * DH + l4);
            acc = make_float4(fmaf(hv.x, sn, bb.x), fmaf(hv.y, sn, bb.y),
                              fmaf(hv.z, sn, bb.z), fmaf(hv.w, sn, bb.w));
        } else {
            acc = make_float4(0.f, 0.f, 0.f, 0.f);
        }

        for (int base = beg; base < end; base += 32) {
            int j = base + lane;
            int2 sw = (j < end) ? g_csr[j] : make_int2(0, 0);  // w=0 => no-op
            int m = end - base;
            if (m > 32) m = 32;
            int jj = 0;
            for (; jj + 4 <= m; jj += 4) {
                int   s0 = __shfl_sync(0xffffffffu, sw.x, jj + half);
                int   s1 = __shfl_sync(0xffffffffu, sw.x, jj + 2 + half);
                float w0 = __int_as_float(__shfl_sync(0xffffffffu, sw.y, jj + half));
                float w1 = __int_as_float(__shfl_sync(0xffffffffu, sw.y, jj + 2 + half));
                float4 v0 = *reinterpret_cast<const float4*>(h + (size_t)s0 * DH + l4);
                float4 v1 = *reinterpret_cast<const float4*>(h + (size_t)s1 * DH + l4);
                acc.x  = fmaf(v0.x, w0, acc.x);  acc.y  = fmaf(v0.y, w0, acc.y);
                acc.z  = fmaf(v0.z, w0, acc.z);  acc.w  = fmaf(v0.w, w0, acc.w);
                acc2.x = fmaf(v1.x, w1, acc2.x); acc2.y = fmaf(v1.y, w1, acc2.y);
                acc2.z = fmaf(v1.z, w1, acc2.z); acc2.w = fmaf(v1.w, w1, acc2.w);
            }
            for (; jj < m; jj += 2) {
                int pick = jj + half;                     // pick <= 31 always
                int   s0 = __shfl_sync(0xffffffffu, sw.x, pick);
                float w0 = __int_as_float(__shfl_sync(0xffffffffu, sw.y, pick));
                float4 v0 = *reinterpret_cast<const float4*>(h + (size_t)s0 * DH + l4);
                acc.x = fmaf(v0.x, w0, acc.x); acc.y = fmaf(v0.y, w0, acc.y);
                acc.z = fmaf(v0.z, w0, acc.z); acc.w = fmaf(v0.w, w0, acc.w);
            }
        }
        acc.x += acc2.x; acc.y += acc2.y; acc.z += acc2.z; acc.w += acc2.w;
        acc.x += __shfl_xor_sync(0xffffffffu, acc.x, 16);
        acc.y += __shfl_xor_sync(0xffffffffu, acc.y, 16);
        acc.z += __shfl_xor_sync(0xffffffffu, acc.z, 16);
        acc.w += __shfl_xor_sync(0xffffffffu, acc.w, 16);
        if (half == 0) {
            *reinterpret_cast<float4*>(agg + (size_t)r * DH + l4) = acc;
            ls0 += acc.x; lq0 = fmaf(acc.x, acc.x, lq0);
            ls1 += acc.y; lq1 = fmaf(acc.y, acc.y, lq1);
            ls2 += acc.z; lq2 = fmaf(acc.z, acc.z, lq2);
            ls3 += acc.w; lq3 = fmaf(acc.w, acc.w, lq3);
        }
    }

    // block reduction of BN stats, then 128 atomics per block
    __shared__ float ssum[8][64], ssq[8][64];
    int w = tid >> 5;
    if (half == 0) {
        ssum[w][l4 + 0] = ls0; ssum[w][l4 + 1] = ls1;
        ssum[w][l4 + 2] = ls2; ssum[w][l4 + 3] = ls3;
        ssq[w][l4 + 0] = lq0;  ssq[w][l4 + 1] = lq1;
        ssq[w][l4 + 2] = lq2;  ssq[w][l4 + 3] = lq3;
    }
    __syncthreads();
    if (tid < 64) {
        float S = 0.f, Q = 0.f;
        #pragma unroll
        for (int ww = 0; ww < 8; ww++) { S += ssum[ww][tid]; Q += ssq[ww][tid]; }
        atomicAdd(&gsum[tid], S);
        atomicAdd(&gsq[tid], Q);
    }
}

// ---------------- GEMM2: h2 = relu(bn1(agg1)) @ W2 ---------------------------
__global__ void gemm2_kernel(const float* __restrict__ W2,
                             const float* __restrict__ gamma1,
                             const float* __restrict__ beta1) {
    __shared__ float sW[DH * DH];   // 16 KB
    __shared__ float sx[32][DH];    // 8 KB
    __shared__ float s_scale[DH], s_shift[DH];
    int tid = threadIdx.x;
    if (tid < DH) {
        float mean = g_sum1[tid] * (1.0f / Nn);
        float var = g_sq1[tid] * (1.0f / Nn) - mean * mean;
        float sc = gamma1[tid] * rsqrtf(var + BN_EPS);
        s_scale[tid] = sc;
        s_shift[tid] = fmaf(-mean, sc, beta1[tid]);
    }
    for (int i = tid; i < DH * DH; i += 256) sW[i] = W2[i];
    __syncthreads();
    int warp = tid >> 5, lane = tid & 31;

    for (int base = blockIdx.x * 32; base < Nn; base += gridDim.x * 32) {
        int r0 = base + warp * 4;
        #pragma unroll
        for (int r = 0; r < 4; r++) {
            int row = r0 + r;
            if (row < Nn) {
                #pragma unroll
                for (int j = 0; j < 2; j++) {
                    int c = lane + j * 32;
                    float v = g_agg1[(size_t)row * DH + c];
                    sx[warp * 4 + r][c] = fmaxf(fmaf(v, s_scale[c], s_shift[c]), 0.f);
                }
            }
        }
        __syncwarp();

        float acc[4][2] = {};
        #pragma unroll 4
        for (int k4 = 0; k4 < DH / 4; k4++) {
            float4 xv[4];
            #pragma unroll
            for (int r = 0; r < 4; r++)
                xv[r] = *reinterpret_cast<const float4*>(&sx[warp * 4 + r][k4 * 4]);
            #pragma unroll
            for (int kk = 0; kk < 4; kk++) {
                int k = k4 * 4 + kk;
                float w0 = sW[k * DH + lane];
                float w1v = sW[k * DH + lane + 32];
                #pragma unroll
                for (int r = 0; r < 4; r++) {
                    float xs = (kk == 0) ? xv[r].x : (kk == 1) ? xv[r].y : (kk == 2) ? xv[r].z : xv[r].w;
                    acc[r][0] = fmaf(xs, w0, acc[r][0]);
                    acc[r][1] = fmaf(xs, w1v, acc[r][1]);
                }
            }
        }

        #pragma unroll
        for (int r = 0; r < 4; r++) {
            int row = r0 + r;
            if (row < Nn) {
                g_h2[row * DH + lane] = acc[r][0];
                g_h2[row * DH + lane + 32] = acc[r][1];
            }
        }
        __syncwarp();
    }
}

// ---------------- final: out = relu(bn2(agg2)) -------------------------------
__global__ void final_kernel(const float* __restrict__ gamma2,
                             const float* __restrict__ beta2,
                             float* __restrict__ out) {
    __shared__ float s_scale[DH], s_shift[DH];
    int tid = threadIdx.x;
    if (tid < DH) {
        float mean = g_sum2[tid] * (1.0f / Nn);
        float var = g_sq2[tid] * (1.0f / Nn) - mean * mean;
        float sc = gamma2[tid] * rsqrtf(var + BN_EPS);
        s_scale[tid] = sc;
        s_shift[tid] = fmaf(-mean, sc, beta2[tid]);
    }
    __syncthreads();
    int i = blockIdx.x * 256 + tid;
    if (i < Nn * DH) {
        int c = i & 63;
        out[i] = fmaxf(fmaf(g_agg2[i], s_scale[c], s_shift[c]), 0.f);
    }
}

// -----------------------------------------------------------------------------
extern "C" void kernel_launch(void* const* d_in, const int* in_sizes, int n_in,
                              void* d_out, int out_size) {
    const float* x      = (const float*)d_in[0];
    const void*  ei_sc  = d_in[1];
    const float* w_sc   = (const float*)d_in[2];
    // d_in[3] = edge_index_fc (unused by reference)
    const float* w_fc   = (const float*)d_in[4];
    const float* alpha  = (const float*)d_in[5];
    const float* W1     = (const float*)d_in[6];
    const float* b1     = (const float*)d_in[7];
    const float* W2     = (const float*)d_in[8];
    const float* b2     = (const float*)d_in[9];
    const float* gamma1 = (const float*)d_in[10];
    const float* beta1  = (const float*)d_in[11];
    const float* gamma2 = (const float*)d_in[12];
    const float* beta2  = (const float*)d_in[13];
    float* out = (float*)d_out;

    const int TB = 256;
    const int nblkN = (Nn + TB - 1) / TB;       // 196
    const int nblkE = (Ee + TB - 1) / TB;       // 6250

    detect_kernel<<<1, TB>>>((const unsigned*)ei_sc);
    init_kernel<<<nblkN, TB>>>(alpha);
    mix_deg_kernel<<<nblkE, TB>>>(ei_sc, w_sc, w_fc);
    dinv_kernel<<<nblkN, TB>>>();
    scan_a_kernel<<<196, TB>>>();
    scan_b_kernel<<<1, TB>>>();
    scan_c_kernel<<<196, TB>>>();
    fill_kernel<<<nblkE, TB>>>();
    gemm1_kernel<<<592, TB>>>(x, W1);
    agg_kernel<1><<<592, TB>>>(b1);
    gemm2_kernel<<<592, TB>>>(W2, gamma1, beta1);
    agg_kernel<2><<<592, TB>>>(b2);
    final_kernel<<<(Nn * DH + TB - 1) / TB, TB>>>(gamma2, beta2, out);
}

// round 9
// speedup vs baseline: 1.4162x; 1.0523x over previous
#include <cuda_runtime.h>
#include <math.h>

#define Nn 50000
#define Ee 1600000
#define DIN 128
#define DH 64
#define BN_EPS 1e-5f

// ---------------- scratch (device globals; no allocation allowed) -------------
__device__ float  g_w[Ee];            // mixed weight (pre-norm)
__device__ int2   g_idx[Ee];          // (src, dst) as int32
__device__ int2   g_csr[Ee];          // dst-sorted: (src, bitcast(norm))
__device__ float2 g_degcnt[Nn];       // (weighted degree incl self, count) via red.v2
__device__ float  g_dinv[Nn];         // rsqrt(deg)
__device__ int    g_part[50176];      // block-local exclusive scan
__device__ int    g_bsum[196], g_boff[256];
__device__ int    g_row_off[Nn + 1];  // CSR row offsets
__device__ int    g_cursor[Nn];       // fill cursors
__device__ float  g_h1[Nn * DH];      // x @ W1
__device__ float  g_agg1[Nn * DH];
__device__ float  g_h2[Nn * DH];
__device__ float  g_agg2[Nn * DH];
__device__ float  g_sum1[DH], g_sq1[DH], g_sum2[DH], g_sq2[DH];
__device__ float  g_a;
__device__ int    g_is64;

// ------------- detect dtype (block 0) + init everything (all blocks) ---------
__global__ void detect_init_kernel(const unsigned* __restrict__ ei,
                                   const float* __restrict__ alpha) {
    int i = blockIdx.x * blockDim.x + threadIdx.x;
    if (i < Nn) g_degcnt[i] = make_float2(1.0f, 0.0f);   // self-loop weight 1
    if (i < DH) { g_sum1[i] = 0.f; g_sq1[i] = 0.f; g_sum2[i] = 0.f; g_sq2[i] = 0.f; }
    if (blockIdx.x == 1 && threadIdx.x == 0) g_a = 1.0f / (1.0f + expf(-alpha[0]));
    if (blockIdx.x == 0) {
        __shared__ unsigned sh[256];
        unsigned o = 0;
        // OR the would-be high words of the first 4096 int64 entries (reads stay
        // within 8192 u32 words < 2*Ee under either dtype).
        for (int k = threadIdx.x; k < 4096; k += 256) o |= ei[2 * k + 1];
        sh[threadIdx.x] = o;
        __syncthreads();
        if (threadIdx.x == 0) {
            unsigned t = 0;
            for (int k = 0; k < 256; k++) t |= sh[k];
            g_is64 = (t == 0) ? 1 : 0;
        }
    }
}

// ---------------- mix weights, record (src,dst), fused degree+count red ------
__global__ void mix_deg_kernel(const void* __restrict__ ei,
                               const float* __restrict__ wsc,
                               const float* __restrict__ wfc) {
    int e = blockIdx.x * blockDim.x + threadIdx.x;
    if (e >= Ee) return;
    int s, d;
    if (g_is64) {
        const long long* p = (const long long*)ei;   // full-8B loads: full sectors
        s = (int)p[e];
        d = (int)p[(size_t)Ee + e];
    } else {
        const int* p = (const int*)ei;
        s = p[e];
        d = p[Ee + e];
    }
    float a = g_a;
    float w = a * wsc[e] + (1.0f - a) * wfc[e];
    g_w[e] = w;
    g_idx[e] = make_int2(s, d);
    float* dp = (float*)&g_degcnt[d];
    asm volatile("red.global.add.v2.f32 [%0], {%1,%2};"
                 :: "l"(dp), "f"(w), "f"(1.0f) : "memory");
}

// ---------------- scan part A (+ dinv fused: same index space) ---------------
__global__ void scan_a_kernel() {
    __shared__ int s[256];
    int i = blockIdx.x * 256 + threadIdx.x;
    int v = 0;
    if (i < Nn) {
        float2 dc = g_degcnt[i];
        v = (int)dc.y;
        g_dinv[i] = (dc.x > 0.f) ? rsqrtf(fmaxf(dc.x, 1e-12f)) : 0.f;
    }
    s[threadIdx.x] = v;
    __syncthreads();
    #pragma unroll
    for (int off = 1; off < 256; off <<= 1) {
        int t = (threadIdx.x >= off) ? s[threadIdx.x - off] : 0;
        __syncthreads();
        s[threadIdx.x] += t;
        __syncthreads();
    }
    g_part[i] = s[threadIdx.x] - v;
    if (threadIdx.x == 255) g_bsum[blockIdx.x] = s[255];
}

__global__ void scan_b_kernel() {
    __shared__ int s[256];
    int v = (threadIdx.x < 196) ? g_bsum[threadIdx.x] : 0;
    s[threadIdx.x] = v;
    __syncthreads();
    #pragma unroll
    for (int off = 1; off < 256; off <<= 1) {
        int t = (threadIdx.x >= off) ? s[threadIdx.x - off] : 0;
        __syncthreads();
        s[threadIdx.x] += t;
        __syncthreads();
    }
    g_boff[threadIdx.x] = s[threadIdx.x] - v;
}

__global__ void scan_c_kernel() {
    int i = blockIdx.x * 256 + threadIdx.x;
    if (i < Nn) {
        int o = g_part[i] + g_boff[blockIdx.x];
        g_row_off[i] = o;
        g_cursor[i] = o;
    }
    if (i == 0) g_row_off[Nn] = Ee;
}

// ---------------- CSR fill: norm computed here -------------------------------
__global__ void fill_kernel() {
    int e = blockIdx.x * blockDim.x + threadIdx.x;
    if (e >= Ee) return;
    int2 sd = g_idx[e];
    float nrm = g_w[e] * g_dinv[sd.x] * g_dinv[sd.y];
    int pos = atomicAdd(&g_cursor[sd.y], 1);
    g_csr[pos] = make_int2(sd.x, __float_as_int(nrm));
}

// ---------------- GEMM1: h1 = x @ W1 -----------------------------------------
__global__ void gemm1_kernel(const float* __restrict__ x,
                             const float* __restrict__ W1) {
    __shared__ float sW[DIN * DH];      // 32 KB
    __shared__ float sx[32][DIN];       // 16 KB
    int tid = threadIdx.x;
    for (int i = tid; i < DIN * DH; i += 256) sW[i] = W1[i];
    __syncthreads();
    int warp = tid >> 5, lane = tid & 31;

    for (int base = blockIdx.x * 32; base < Nn; base += gridDim.x * 32) {
        int r0 = base + warp * 4;
        #pragma unroll
        for (int r = 0; r < 4; r++) {
            int row = r0 + r;
            if (row < Nn) {
                #pragma unroll
                for (int j = 0; j < 4; j++)
                    sx[warp * 4 + r][lane + j * 32] = x[(size_t)row * DIN + lane + j * 32];
            }
        }
        __syncwarp();

        float acc[4][2] = {};
        #pragma unroll 8
        for (int k4 = 0; k4 < DIN / 4; k4++) {
            float4 xv[4];
            #pragma unroll
            for (int r = 0; r < 4; r++)
                xv[r] = *reinterpret_cast<const float4*>(&sx[warp * 4 + r][k4 * 4]);
            #pragma unroll
            for (int kk = 0; kk < 4; kk++) {
                int k = k4 * 4 + kk;
                float w0 = sW[k * DH + lane];
                float w1v = sW[k * DH + lane + 32];
                #pragma unroll
                for (int r = 0; r < 4; r++) {
                    float xs = (kk == 0) ? xv[r].x : (kk == 1) ? xv[r].y : (kk == 2) ? xv[r].z : xv[r].w;
                    acc[r][0] = fmaf(xs, w0, acc[r][0]);
                    acc[r][1] = fmaf(xs, w1v, acc[r][1]);
                }
            }
        }

        #pragma unroll
        for (int r = 0; r < 4; r++) {
            int row = r0 + r;
            if (row < Nn) {
                g_h1[row * DH + lane] = acc[r][0];
                g_h1[row * DH + lane + 32] = acc[r][1];
            }
        }
        __syncwarp();
    }
}

// ---------------- CSR aggregation + fused BN stats ---------------------------
// One warp per dst row; half-warps (16 lanes x float4 = full 64-col row) process
// interleaved edges with 4 independent accumulators. Edge metadata is staged in
// shared memory (coalesced LDG + STS once per 32 edges) and read back with
// broadcast LDS -> no shuffles in the hot loop.
template <int L>
__global__ void agg_kernel(const float* __restrict__ bias) {
    const float* __restrict__ h = (L == 1) ? g_h1 : g_h2;
    float* agg  = (L == 1) ? g_agg1 : g_agg2;
    float* gsum = (L == 1) ? g_sum1 : g_sum2;
    float* gsq  = (L == 1) ? g_sq1  : g_sq2;

    __shared__ int2 stage[8][32];     // 2 KB: per-warp staging of CSR entries

    int tid = threadIdx.x;
    int w = tid >> 5, lane = tid & 31, half = lane >> 4;
    int l4 = (lane & 15) * 4;
    int wg = (blockIdx.x << 3) + w;            // global warp id (blockDim=256)
    int nw = gridDim.x << 3;
    float4 bb = *reinterpret_cast<const float4*>(bias + l4);
    float ls0 = 0, ls1 = 0, ls2 = 0, ls3 = 0;
    float lq0 = 0, lq1 = 0, lq2 = 0, lq3 = 0;

    for (int r = wg; r < Nn; r += nw) {
        int beg = g_row_off[r], end = g_row_off[r + 1];
        float4 a0, a1, a2, a3;
        a1 = a2 = a3 = make_float4(0.f, 0.f, 0.f, 0.f);
        if (half == 0) {
            float di = g_dinv[r];
            float sn = di * di;  // self-loop: dinv*1*dinv
            float4 hv = *reinterpret_cast<const float4*>(h + (size_t)r * DH + l4);
            a0 = make_float4(fmaf(hv.x, sn, bb.x), fmaf(hv.y, sn, bb.y),
                             fmaf(hv.z, sn, bb.z), fmaf(hv.w, sn, bb.w));
        } else {
            a0 = make_float4(0.f, 0.f, 0.f, 0.f);
        }

        for (int base = beg; base < end; base += 32) {
            int m = end - base;
            if (m > 32) m = 32;
            // stage up to 32 entries; pad with zero-weight entries (src 0 is a
            // valid address, weight 0 makes the FMA a no-op)
            stage[w][lane] = (lane < m) ? g_csr[base + lane] : make_int2(0, 0);
            __syncwarp();

            int jj = 0;
            for (; jj + 8 <= m; jj += 8) {
                int2 e0 = stage[w][jj + half];
                int2 e1 = stage[w][jj + 2 + half];
                int2 e2 = stage[w][jj + 4 + half];
                int2 e3 = stage[w][jj + 6 + half];
                float4 v0 = *reinterpret_cast<const float4*>(h + (size_t)e0.x * DH + l4);
                float4 v1 = *reinterpret_cast<const float4*>(h + (size_t)e1.x * DH + l4);
                float4 v2 = *reinterpret_cast<const float4*>(h + (size_t)e2.x * DH + l4);
                float4 v3 = *reinterpret_cast<const float4*>(h + (size_t)e3.x * DH + l4);
                float w0 = __int_as_float(e0.y), w1 = __int_as_float(e1.y);
                float w2 = __int_as_float(e2.y), w3 = __int_as_float(e3.y);
                a0.x = fmaf(v0.x, w0, a0.x); a0.y = fmaf(v0.y, w0, a0.y);
                a0.z = fmaf(v0.z, w0, a0.z); a0.w = fmaf(v0.w, w0, a0.w);
                a1.x = fmaf(v1.x, w1, a1.x); a1.y = fmaf(v1.y, w1, a1.y);
                a1.z = fmaf(v1.z, w1, a1.z); a1.w = fmaf(v1.w, w1, a1.w);
                a2.x = fmaf(v2.x, w2, a2.x); a2.y = fmaf(v2.y, w2, a2.y);
                a2.z = fmaf(v2.z, w2, a2.z); a2.w = fmaf(v2.w, w2, a2.w);
                a3.x = fmaf(v3.x, w3, a3.x); a3.y = fmaf(v3.y, w3, a3.y);
                a3.z = fmaf(v3.z, w3, a3.z); a3.w = fmaf(v3.w, w3, a3.w);
            }
            if (jj < m) {
                // padded tail: processes edges jj..jj+7 (pads are weight-0 no-ops)
                int2 e0 = stage[w][jj + half];
                int2 e1 = stage[w][jj + 2 + half];
                int2 e2 = stage[w][jj + 4 + half];
                int2 e3 = stage[w][jj + 6 + half];
                float4 v0 = *reinterpret_cast<const float4*>(h + (size_t)e0.x * DH + l4);
                float4 v1 = *reinterpret_cast<const float4*>(h + (size_t)e1.x * DH + l4);
                float4 v2 = *reinterpret_cast<const float4*>(h + (size_t)e2.x * DH + l4);
                float4 v3 = *reinterpret_cast<const float4*>(h + (size_t)e3.x * DH + l4);
                float w0 = __int_as_float(e0.y), w1 = __int_as_float(e1.y);
                float w2 = __int_as_float(e2.y), w3 = __int_as_float(e3.y);
                a0.x = fmaf(v0.x, w0, a0.x); a0.y = fmaf(v0.y, w0, a0.y);
                a0.z = fmaf(v0.z, w0, a0.z); a0.w = fmaf(v0.w, w0, a0.w);
                a1.x = fmaf(v1.x, w1, a1.x); a1.y = fmaf(v1.y, w1, a1.y);
                a1.z = fmaf(v1.z, w1, a1.z); a1.w = fmaf(v1.w, w1, a1.w);
                a2.x = fmaf(v2.x, w2, a2.x); a2.y = fmaf(v2.y, w2, a2.y);
                a2.z = fmaf(v2.z, w2, a2.z); a2.w = fmaf(v2.w, w2, a2.w);
                a3.x = fmaf(v3.x, w3, a3.x); a3.y = fmaf(v3.y, w3, a3.y);
                a3.z = fmaf(v3.z, w3, a3.z); a3.w = fmaf(v3.w, w3, a3.w);
            }
            __syncwarp();   // staging buffer reused next chunk
        }

        float4 acc = make_float4(a0.x + a1.x + a2.x + a3.x,
                                 a0.y + a1.y + a2.y + a3.y,
                                 a0.z + a1.z + a2.z + a3.z,
                                 a0.w + a1.w + a2.w + a3.w);
        acc.x += __shfl_xor_sync(0xffffffffu, acc.x, 16);
        acc.y += __shfl_xor_sync(0xffffffffu, acc.y, 16);
        acc.z += __shfl_xor_sync(0xffffffffu, acc.z, 16);
        acc.w += __shfl_xor_sync(0xffffffffu, acc.w, 16);
        if (half == 0) {
            *reinterpret_cast<float4*>(agg + (size_t)r * DH + l4) = acc;
            ls0 += acc.x; lq0 = fmaf(acc.x, acc.x, lq0);
            ls1 += acc.y; lq1 = fmaf(acc.y, acc.y, lq1);
            ls2 += acc.z; lq2 = fmaf(acc.z, acc.z, lq2);
            ls3 += acc.w; lq3 = fmaf(acc.w, acc.w, lq3);
        }
    }

    // block reduction of BN stats, then 128 atomics per block
    __shared__ float ssum[8][64], ssq[8][64];
    if (half == 0) {
        ssum[w][l4 + 0] = ls0; ssum[w][l4 + 1] = ls1;
        ssum[w][l4 + 2] = ls2; ssum[w][l4 + 3] = ls3;
        ssq[w][l4 + 0] = lq0;  ssq[w][l4 + 1] = lq1;
        ssq[w][l4 + 2] = lq2;  ssq[w][l4 + 3] = lq3;
    }
    __syncthreads();
    if (tid < 64) {
        float S = 0.f, Q = 0.f;
        #pragma unroll
        for (int ww = 0; ww < 8; ww++) { S += ssum[ww][tid]; Q += ssq[ww][tid]; }
        atomicAdd(&gsum[tid], S);
        atomicAdd(&gsq[tid], Q);
    }
}

// ---------------- GEMM2: h2 = relu(bn1(agg1)) @ W2 ---------------------------
__global__ void gemm2_kernel(const float* __restrict__ W2,
                             const float* __restrict__ gamma1,
                             const float* __restrict__ beta1) {
    __shared__ float sW[DH * DH];   // 16 KB
    __shared__ float sx[32][DH];    // 8 KB
    __shared__ float s_scale[DH], s_shift[DH];
    int tid = threadIdx.x;
    if (tid < DH) {
        float mean = g_sum1[tid] * (1.0f / Nn);
        float var = g_sq1[tid] * (1.0f / Nn) - mean * mean;
        float sc = gamma1[tid] * rsqrtf(var + BN_EPS);
        s_scale[tid] = sc;
        s_shift[tid] = fmaf(-mean, sc, beta1[tid]);
    }
    for (int i = tid; i < DH * DH; i += 256) sW[i] = W2[i];
    __syncthreads();
    int warp = tid >> 5, lane = tid & 31;

    for (int base = blockIdx.x * 32; base < Nn; base += gridDim.x * 32) {
        int r0 = base + warp * 4;
        #pragma unroll
        for (int r = 0; r < 4; r++) {
            int row = r0 + r;
            if (row < Nn) {
                #pragma unroll
                for (int j = 0; j < 2; j++) {
                    int c = lane + j * 32;
                    float v = g_agg1[(size_t)row * DH + c];
                    sx[warp * 4 + r][c] = fmaxf(fmaf(v, s_scale[c], s_shift[c]), 0.f);
                }
            }
        }
        __syncwarp();

        float acc[4][2] = {};
        #pragma unroll 4
        for (int k4 = 0; k4 < DH / 4; k4++) {
            float4 xv[4];
            #pragma unroll
            for (int r = 0; r < 4; r++)
                xv[r] = *reinterpret_cast<const float4*>(&sx[warp * 4 + r][k4 * 4]);
            #pragma unroll
            for (int kk = 0; kk < 4; kk++) {
                int k = k4 * 4 + kk;
                float w0 = sW[k * DH + lane];
                float w1v = sW[k * DH + lane + 32];
                #pragma unroll
                for (int r = 0; r < 4; r++) {
                    float xs = (kk == 0) ? xv[r].x : (kk == 1) ? xv[r].y : (kk == 2) ? xv[r].z : xv[r].w;
                    acc[r][0] = fmaf(xs, w0, acc[r][0]);
                    acc[r][1] = fmaf(xs, w1v, acc[r][1]);
                }
            }
        }

        #pragma unroll
        for (int r = 0; r < 4; r++) {
            int row = r0 + r;
            if (row < Nn) {
                g_h2[row * DH + lane] = acc[r][0];
                g_h2[row * DH + lane + 32] = acc[r][1];
            }
        }
        __syncwarp();
    }
}

// ---------------- final: out = relu(bn2(agg2)) -------------------------------
__global__ void final_kernel(const float* __restrict__ gamma2,
                             const float* __restrict__ beta2,
                             float* __restrict__ out) {
    __shared__ float s_scale[DH], s_shift[DH];
    int tid = threadIdx.x;
    if (tid < DH) {
        float mean = g_sum2[tid] * (1.0f / Nn);
        float var = g_sq2[tid] * (1.0f / Nn) - mean * mean;
        float sc = gamma2[tid] * rsqrtf(var + BN_EPS);
        s_scale[tid] = sc;
        s_shift[tid] = fmaf(-mean, sc, beta2[tid]);
    }
    __syncthreads();
    int i = blockIdx.x * 256 + tid;
    if (i < Nn * DH) {
        int c = i & 63;
        out[i] = fmaxf(fmaf(g_agg2[i], s_scale[c], s_shift[c]), 0.f);
    }
}

// -----------------------------------------------------------------------------
extern "C" void kernel_launch(void* const* d_in, const int* in_sizes, int n_in,
                              void* d_out, int out_size) {
    const float* x      = (const float*)d_in[0];
    const void*  ei_sc  = d_in[1];
    const float* w_sc   = (const float*)d_in[2];
    // d_in[3] = edge_index_fc (unused by reference)
    const float* w_fc   = (const float*)d_in[4];
    const float* alpha  = (const float*)d_in[5];
    const float* W1     = (const float*)d_in[6];
    const float* b1     = (const float*)d_in[7];
    const float* W2     = (const float*)d_in[8];
    const float* b2     = (const float*)d_in[9];
    const float* gamma1 = (const float*)d_in[10];
    const float* beta1  = (const float*)d_in[11];
    const float* gamma2 = (const float*)d_in[12];
    const float* beta2  = (const float*)d_in[13];
    float* out = (float*)d_out;

    const int TB = 256;
    const int nblkE = (Ee + TB - 1) / TB;       // 6250

    detect_init_kernel<<<196, TB>>>((const unsigned*)ei_sc, alpha);
    mix_deg_kernel<<<nblkE, TB>>>(ei_sc, w_sc, w_fc);
    scan_a_kernel<<<196, TB>>>();
    scan_b_kernel<<<1, TB>>>();
    scan_c_kernel<<<196, TB>>>();
    fill_kernel<<<nblkE, TB>>>();
    gemm1_kernel<<<592, TB>>>(x, W1);
    agg_kernel<1><<<592, TB>>>(b1);
    gemm2_kernel<<<592, TB>>>(W2, gamma1, beta1);
    agg_kernel<2><<<592, TB>>>(b2);
    final_kernel<<<(Nn * DH + TB - 1) / TB, TB>>>(gamma2, beta2, out);
}